// round 2
// baseline (speedup 1.0000x reference)
#include <cuda_runtime.h>
#include <math.h>

#define NXC 49152
#define NYC 50000
#define NY_PAD 50048
#define CDIM 128
#define KTOP 10
#define NSPLIT 4
#define NY_SPLIT 12500
#define NTILES 98          // ceil(12500/128)
#define BM 128
#define BN 128
#define NXK (NXC*KTOP)
#define INV_TAU 20.0f

// ---------------- device scratch (no allocations allowed) ----------------
__device__ float g_xT[CDIM * NXC];        // normalized x, [k][m]
__device__ float g_yT[CDIM * NY_PAD];     // normalized y, [k][n], padded
__device__ float g_sV[NSPLIT * KTOP * NXC];
__device__ int   g_sI[NSPLIT * KTOP * NXC];

// ---------------- helpers ----------------
__device__ __forceinline__ unsigned long long pk2(float x) {
    unsigned long long r;
    asm("mov.b64 %0, {%1, %1};" : "=l"(r) : "f"(x));
    return r;
}
__device__ __forceinline__ void ffma2(unsigned long long& d,
                                      unsigned long long a,
                                      unsigned long long b) {
    asm("fma.rn.f32x2 %0, %1, %2, %0;" : "+l"(d) : "l"(a), "l"(b));
}

__device__ __forceinline__ void insert10(float (&tv)[10], int (&ti)[10], float v, int j) {
    tv[9] = v; ti[9] = j;
#pragma unroll
    for (int s = 9; s > 0; --s) {
        bool sw = (tv[s] > tv[s-1]) || (tv[s] == tv[s-1] && ti[s] < ti[s-1]);
        if (sw) {
            float fv = tv[s]; tv[s] = tv[s-1]; tv[s-1] = fv;
            int   fi = ti[s]; ti[s] = ti[s-1]; ti[s-1] = fi;
        }
    }
}

// ---------------- normalize + transpose ----------------
__global__ void norm_x_kernel(const float* __restrict__ in) {
    int warp = (blockIdx.x * blockDim.x + threadIdx.x) >> 5;
    int lane = threadIdx.x & 31;
    if (warp >= NXC) return;
    float4 v = *(const float4*)&in[warp * CDIM + lane * 4];
    float ss = v.x*v.x + v.y*v.y + v.z*v.z + v.w*v.w;
#pragma unroll
    for (int o = 16; o > 0; o >>= 1) ss += __shfl_xor_sync(0xffffffffu, ss, o);
    float inv = 1.0f / fmaxf(sqrtf(ss), 1e-12f);
    g_xT[(lane*4+0) * NXC + warp] = v.x * inv;
    g_xT[(lane*4+1) * NXC + warp] = v.y * inv;
    g_xT[(lane*4+2) * NXC + warp] = v.z * inv;
    g_xT[(lane*4+3) * NXC + warp] = v.w * inv;
}

__global__ void norm_y_kernel(const float* __restrict__ in) {
    int warp = (blockIdx.x * blockDim.x + threadIdx.x) >> 5;
    int lane = threadIdx.x & 31;
    if (warp >= NY_PAD) return;
    if (warp >= NYC) {
#pragma unroll
        for (int c = 0; c < 4; c++) g_yT[(lane*4+c) * NY_PAD + warp] = 0.0f;
        return;
    }
    float4 v = *(const float4*)&in[warp * CDIM + lane * 4];
    float ss = v.x*v.x + v.y*v.y + v.z*v.z + v.w*v.w;
#pragma unroll
    for (int o = 16; o > 0; o >>= 1) ss += __shfl_xor_sync(0xffffffffu, ss, o);
    float inv = 1.0f / fmaxf(sqrtf(ss), 1e-12f);
    g_yT[(lane*4+0) * NY_PAD + warp] = v.x * inv;
    g_yT[(lane*4+1) * NY_PAD + warp] = v.y * inv;
    g_yT[(lane*4+2) * NY_PAD + warp] = v.z * inv;
    g_yT[(lane*4+3) * NY_PAD + warp] = v.w * inv;
}

// ---------------- y-tile prefetch via cp.async ----------------
__device__ __forceinline__ void cp_tile(float* ys, int n0, int tid) {
#pragma unroll
    for (int i = 0; i < 16; i++) {
        int idx = tid + 256 * i;          // 0..4095 (16B units)
        int k = idx >> 5;
        int q = idx & 31;
        unsigned sdst = (unsigned)__cvta_generic_to_shared(&ys[k * 128 + q * 4]);
        const float* gsrc = &g_yT[k * NY_PAD + n0 + q * 4];
        asm volatile("cp.async.cg.shared.global [%0], [%1], 16;" :: "r"(sdst), "l"(gsrc));
    }
    asm volatile("cp.async.commit_group;" ::: "memory");
}

// ---------------- main GEMM + streaming top-k ----------------
__global__ __launch_bounds__(256) void simtopk_kernel() {
    extern __shared__ float sm[];
    float* xs = sm;            // [128][128] k-major  (64 KB)
    float* ys = sm + 16384;    // [128][128] k-major  (64 KB)
    float* sb = sm + 32768;    // sim tile [row][col] (64 KB)

    const int tid = threadIdx.x;
    const int mt = blockIdx.x;
    const int split = blockIdx.y;
    const int m0 = mt * BM;
    const int nbase = split * NY_SPLIT;
    const int nend = nbase + NY_SPLIT;

    // load x tile (k-major, coalesced)
#pragma unroll
    for (int i = 0; i < 16; i++) {
        int idx = tid + 256 * i;
        int k = idx >> 5;
        int mo = (idx & 31) << 2;
        *(float4*)&xs[k * 128 + mo] = *(const float4*)&g_xT[k * NXC + m0 + mo];
    }
    cp_tile(ys, nbase, tid);   // prefetch tile 0

    const int ty = tid >> 4;
    const int tx = tid & 15;
    const int row = tid & 127;
    const int half = tid >> 7;
    const int lane = tid & 31;

    float tv[10]; int ti[10];
#pragma unroll
    for (int q = 0; q < 10; q++) { tv[q] = -__int_as_float(0x7f800000); ti[q] = 0x7fffffff; }

    const float* xrow = xs + (ty << 3);
    const float* yrow = ys + (tx << 3);

    for (int t = 0; t < NTILES; t++) {
        int n0 = nbase + t * 128;
        asm volatile("cp.async.wait_group 0;" ::: "memory");
        __syncthreads();

        unsigned long long acc[8][4];
#pragma unroll
        for (int i = 0; i < 8; i++)
#pragma unroll
            for (int p = 0; p < 4; p++) acc[i][p] = 0ull;

#pragma unroll 8
        for (int k = 0; k < 128; k++) {
            float4 a0 = *(const float4*)(xrow + k * 128);
            float4 a1 = *(const float4*)(xrow + k * 128 + 4);
            ulonglong2 b01 = *(const ulonglong2*)(yrow + k * 128);      // cols +0..3
            ulonglong2 b23 = *(const ulonglong2*)(yrow + k * 128 + 4);  // cols +4..7 (FIXED)
            unsigned long long ad[8];
            ad[0] = pk2(a0.x); ad[1] = pk2(a0.y); ad[2] = pk2(a0.z); ad[3] = pk2(a0.w);
            ad[4] = pk2(a1.x); ad[5] = pk2(a1.y); ad[6] = pk2(a1.z); ad[7] = pk2(a1.w);
#pragma unroll
            for (int i = 0; i < 8; i++) {
                ffma2(acc[i][0], ad[i], b01.x);
                ffma2(acc[i][1], ad[i], b01.y);
                ffma2(acc[i][2], ad[i], b23.x);
                ffma2(acc[i][3], ad[i], b23.y);
            }
        }
        __syncthreads();                       // ys fully consumed
        if (t + 1 < NTILES) cp_tile(ys, nbase + (t + 1) * 128, tid);

        // spill sim tile to smem
#pragma unroll
        for (int i = 0; i < 8; i++) {
            float f[8];
#pragma unroll
            for (int p = 0; p < 4; p++) {
                f[2*p]   = __uint_as_float((unsigned)(acc[i][p] & 0xffffffffull));
                f[2*p+1] = __uint_as_float((unsigned)(acc[i][p] >> 32));
            }
            int r = (ty << 3) + i;
            float4* d = (float4*)&sb[r * 128 + (tx << 3)];
            d[0] = make_float4(f[0], f[1], f[2], f[3]);
            d[1] = make_float4(f[4], f[5], f[6], f[7]);
        }
        __syncthreads();

        // streaming top-k: 2 threads per row, skewed conflict-free scan
#pragma unroll 4
        for (int s = 0; s < 64; s++) {
            int col = (half << 6) + ((s + lane) & 63);
            float v = sb[row * 128 + col];
            int j = n0 + col;
            if (j < nend) {
                if (v > tv[9] || (v == tv[9] && j < ti[9])) insert10(tv, ti, v, j);
            }
        }
        // next-iter top-of-loop sync orders scan before sim rewrite
    }
    __syncthreads();

    // merge the two half-row lists
    if (half == 1) {
#pragma unroll
        for (int q = 0; q < 10; q++) {
            sb[row * 32 + q]      = tv[q];
            sb[row * 32 + 16 + q] = __int_as_float(ti[q]);
        }
    }
    __syncthreads();
    if (half == 0) {
        int ia = 0, ib = 0;
        int m = m0 + row;
#pragma unroll
        for (int q = 0; q < 10; q++) {
            float vb = sb[row * 32 + ib];
            int   jb = __float_as_int(sb[row * 32 + 16 + ib]);
            float va = tv[ia];
            int   ja = ti[ia];
            bool A = (va > vb) || (va == vb && ja < jb);
            float mv = A ? va : vb;
            int   mi = A ? ja : jb;
            if (A) ia++; else ib++;
            g_sV[(split * 10 + q) * NXC + m] = mv;
            g_sI[(split * 10 + q) * NXC + m] = mi;
        }
    }
}

// ---------------- 4-way merge + softmax + COO write ----------------
__global__ void merge_kernel(float* __restrict__ out) {
    int m = blockIdx.x * blockDim.x + threadIdx.x;
    if (m >= NXC) return;
    float lv[4][10]; int li[4][10];
#pragma unroll
    for (int s = 0; s < 4; s++)
#pragma unroll
        for (int q = 0; q < 10; q++) {
            lv[s][q] = g_sV[(s * 10 + q) * NXC + m];
            li[s][q] = g_sI[(s * 10 + q) * NXC + m];
        }
    int h[4] = {0, 0, 0, 0};
    float mv[10]; int mi[10];
#pragma unroll
    for (int q = 0; q < 10; q++) {
        float bv = -__int_as_float(0x7f800000);
        int bj = 0x7fffffff, bs = 0;
#pragma unroll
        for (int s = 0; s < 4; s++) {
            if (h[s] < 10) {
                float v = lv[s][h[s]];
                int   j = li[s][h[s]];
                if (v > bv || (v == bv && j < bj)) { bv = v; bj = j; bs = s; }
            }
        }
        h[bs]++;
        mv[q] = bv; mi[q] = bj;
    }
    float mx = mv[0];
    float e[10], sum = 0.0f;
#pragma unroll
    for (int q = 0; q < 10; q++) { e[q] = expf((mv[q] - mx) * INV_TAU); sum += e[q]; }
    float inv = 1.0f / sum;
#pragma unroll
    for (int q = 0; q < 10; q++) {
        out[m * 10 + q]            = e[q] * inv;
        out[NXK + m * 10 + q]      = (float)m;
        out[2 * NXK + m * 10 + q]  = (float)mi[q];
    }
}

// ---------------- launch ----------------
extern "C" void kernel_launch(void* const* d_in, const int* in_sizes, int n_in,
                              void* d_out, int out_size) {
    const float* fx = (const float*)d_in[0];
    const float* fy = (const float*)d_in[1];
    if (n_in >= 2 && in_sizes[0] == NYC * CDIM && in_sizes[1] == NXC * CDIM) {
        const float* t = fx; fx = fy; fy = t;   // defensive: input order swap
    }
    float* outF = (float*)d_out;

    cudaFuncSetAttribute(simtopk_kernel,
                         cudaFuncAttributeMaxDynamicSharedMemorySize, 196608);

    norm_x_kernel<<<NXC / 8, 256>>>(fx);
    norm_y_kernel<<<NY_PAD / 8, 256>>>(fy);
    simtopk_kernel<<<dim3(NXC / BM, NSPLIT), 256, 196608>>>();
    merge_kernel<<<(NXC + 255) / 256, 256>>>(outF);
}

// round 5
// speedup vs baseline: 1.7397x; 1.7397x over previous
#include <cuda_runtime.h>
#include <math.h>

#define NXC 49152
#define NYC 50000
#define NT_Y 391
#define NY_PAD (NT_Y*128)          // 50048
#define CDIM 128
#define KTOP 10
#define DEPTH 12
#define NSPLIT 4
#define TILES_PER_SPLIT 98
#define NCAND (NSPLIT*2*DEPTH)     // 96
#define NXK (NXC*KTOP)
#define INV_TAU 20.0f

// ---------------- device scratch ----------------
__device__ float    g_x32[NXC*CDIM];      // normalized x, row-major (exact fp32)
__device__ float    g_y32[NY_PAD*CDIM];   // normalized y, row-major, zero-padded
__device__ unsigned g_xP[NXC*CDIM];       // tf32 A fragments, packed
__device__ unsigned g_yP[NY_PAD*CDIM];    // tf32 B fragments, packed
__device__ int      g_candI[NXC*NCAND];   // candidate cols per row

// ---------------- helpers ----------------
__device__ __forceinline__ unsigned tf32_of(float f) {
    unsigned u; asm("cvt.rna.tf32.f32 %0, %1;" : "=r"(u) : "f"(f)); return u;
}

__device__ __forceinline__ void mma_tf32(float (&c)[4], const uint4& a, const uint2& b) {
    asm volatile(
        "mma.sync.aligned.m16n8k8.row.col.f32.tf32.tf32.f32 "
        "{%0,%1,%2,%3}, {%4,%5,%6,%7}, {%8,%9}, {%0,%1,%2,%3};"
        : "+f"(c[0]), "+f"(c[1]), "+f"(c[2]), "+f"(c[3])
        : "r"(a.x), "r"(a.y), "r"(a.z), "r"(a.w), "r"(b.x), "r"(b.y));
}

__device__ __forceinline__ void insert12(float (&tv)[12], int (&ti)[12], float v, int j) {
    tv[11] = v; ti[11] = j;
#pragma unroll
    for (int s = 11; s > 0; --s) {
        bool sw = (tv[s] > tv[s-1]) || (tv[s] == tv[s-1] && ti[s] < ti[s-1]);
        if (sw) {
            float fv = tv[s]; tv[s] = tv[s-1]; tv[s-1] = fv;
            int   fi = ti[s]; ti[s] = ti[s-1]; ti[s-1] = fi;
        }
    }
}

__device__ __forceinline__ void insert10(float (&tv)[10], int (&ti)[10], float v, int j) {
    tv[9] = v; ti[9] = j;
#pragma unroll
    for (int s = 9; s > 0; --s) {
        bool sw = (tv[s] > tv[s-1]) || (tv[s] == tv[s-1] && ti[s] < ti[s-1]);
        if (sw) {
            float fv = tv[s]; tv[s] = tv[s-1]; tv[s-1] = fv;
            int   fi = ti[s]; ti[s] = ti[s-1]; ti[s-1] = fi;
        }
    }
}

// ---------------- normalize (row-major out; EXACT same arithmetic as R2) ----------------
__global__ void norm_x_kernel(const float* __restrict__ in) {
    int warp = (blockIdx.x * blockDim.x + threadIdx.x) >> 5;
    int lane = threadIdx.x & 31;
    if (warp >= NXC) return;
    float4 v = *(const float4*)&in[warp * CDIM + lane * 4];
    float ss = v.x*v.x + v.y*v.y + v.z*v.z + v.w*v.w;
#pragma unroll
    for (int o = 16; o > 0; o >>= 1) ss += __shfl_xor_sync(0xffffffffu, ss, o);
    float inv = 1.0f / fmaxf(sqrtf(ss), 1e-12f);
    float4 o4 = make_float4(v.x*inv, v.y*inv, v.z*inv, v.w*inv);
    *(float4*)&g_x32[warp * CDIM + lane * 4] = o4;
}

__global__ void norm_y_kernel(const float* __restrict__ in) {
    int warp = (blockIdx.x * blockDim.x + threadIdx.x) >> 5;
    int lane = threadIdx.x & 31;
    if (warp >= NY_PAD) return;
    if (warp >= NYC) {
        *(float4*)&g_y32[warp * CDIM + lane * 4] = make_float4(0.f, 0.f, 0.f, 0.f);
        return;
    }
    float4 v = *(const float4*)&in[warp * CDIM + lane * 4];
    float ss = v.x*v.x + v.y*v.y + v.z*v.z + v.w*v.w;
#pragma unroll
    for (int o = 16; o > 0; o >>= 1) ss += __shfl_xor_sync(0xffffffffu, ss, o);
    float inv = 1.0f / fmaxf(sqrtf(ss), 1e-12f);
    float4 o4 = make_float4(v.x*inv, v.y*inv, v.z*inv, v.w*inv);
    *(float4*)&g_y32[warp * CDIM + lane * 4] = o4;
}

// ---------------- tf32 fragment packing ----------------
// A frag (m16n8k8.tf32): lane holds (r0,c0),(r0+8,c0),(r0,c0+4),(r0+8,c0+4); r0=lane>>2, c0=lane&3
__global__ void pack_x_kernel() {
    int t = blockIdx.x * blockDim.x + threadIdx.x;
    if (t >= NXC * 32) return;
    int mf = t >> 9, rem = t & 511, k8 = rem >> 5, lane = rem & 31;
    int r0 = mf * 16 + (lane >> 2);
    int k0 = k8 * 8 + (lane & 3);
    uint4 a;
    a.x = tf32_of(g_x32[r0 * CDIM + k0]);
    a.y = tf32_of(g_x32[(r0 + 8) * CDIM + k0]);
    a.z = tf32_of(g_x32[r0 * CDIM + k0 + 4]);
    a.w = tf32_of(g_x32[(r0 + 8) * CDIM + k0 + 4]);
    ((uint4*)g_xP)[t] = a;
}

// B frag: lane holds (k=lane&3, n=lane>>2) and (k+4, n)
__global__ void pack_y_kernel() {
    int t = blockIdx.x * blockDim.x + threadIdx.x;
    if (t >= (NY_PAD / 8) * 512) return;
    int nf = t >> 9, rem = t & 511, k8 = rem >> 5, lane = rem & 31;
    int n = nf * 8 + (lane >> 2);
    int k = k8 * 8 + (lane & 3);
    uint2 b;
    b.x = tf32_of(g_y32[n * CDIM + k]);
    b.y = tf32_of(g_y32[n * CDIM + k + 4]);
    ((uint2*)g_yP)[t] = b;
}

// ---------------- B tile cp.async (64KB contiguous) ----------------
__device__ __forceinline__ void cp_B(unsigned* Bs, int t, int tid) {
    const unsigned* src = g_yP + (size_t)t * 16384;
#pragma unroll
    for (int i = 0; i < 16; i++) {
        int idx = tid + 256 * i;
        unsigned sdst = (unsigned)__cvta_generic_to_shared(&Bs[idx * 4]);
        asm volatile("cp.async.cg.shared.global [%0], [%1], 16;" :: "r"(sdst), "l"(src + idx * 4));
    }
    asm volatile("cp.async.commit_group;" ::: "memory");
}

// ---------------- tf32 GEMM + streaming candidate top-12 ----------------
__global__ __launch_bounds__(256, 1) void gemm_topk_kernel() {
    extern __shared__ unsigned smu[];
    unsigned* As = smu;                   // 16384 u32 (64KB)
    unsigned* Bs = smu + 16384;           // 16384 u32 (64KB)
    float* sb = (float*)(smu + 32768);    // 128 x 136 floats (68KB)

    const int tid  = threadIdx.x;
    const int lane = tid & 31;
    const int w    = tid >> 5;
    const int wm   = w >> 2;              // 0..1
    const int wn   = w & 3;               // 0..3
    const int mtile = blockIdx.x;
    const int split = blockIdx.y;
    const int t_lo = split * TILES_PER_SPLIT;
    const int t_hi = min(NT_Y, t_lo + TILES_PER_SPLIT);

    // load A tile (fragment-packed, contiguous 64KB)
    {
        const unsigned* src = g_xP + (size_t)mtile * 16384;
#pragma unroll
        for (int i = 0; i < 16; i++) {
            int idx = tid + 256 * i;
            unsigned sdst = (unsigned)__cvta_generic_to_shared(&As[idx * 4]);
            asm volatile("cp.async.cg.shared.global [%0], [%1], 16;" :: "r"(sdst), "l"(src + idx * 4));
        }
        asm volatile("cp.async.commit_group;" ::: "memory");
    }
    cp_B(Bs, t_lo, tid);

    const int row  = tid & 127;
    const int half = tid >> 7;

    float tv[12]; int ti[12];
#pragma unroll
    for (int q = 0; q < 12; q++) { tv[q] = -__int_as_float(0x7f800000); ti[q] = 0x7fffffff; }

    for (int t = t_lo; t < t_hi; ++t) {
        asm volatile("cp.async.wait_group 0;" ::: "memory");
        __syncthreads();

        float acc[4][4][4];
#pragma unroll
        for (int mi = 0; mi < 4; mi++)
#pragma unroll
            for (int ni = 0; ni < 4; ni++)
#pragma unroll
                for (int p = 0; p < 4; p++) acc[mi][ni][p] = 0.0f;

#pragma unroll
        for (int k8 = 0; k8 < 16; k8++) {
            uint4 a[4]; uint2 b[4];
#pragma unroll
            for (int mi = 0; mi < 4; mi++) {
                int mf = wm * 4 + mi;
                a[mi] = *(const uint4*)&As[((mf * 16 + k8) * 32 + lane) * 4];
            }
#pragma unroll
            for (int ni = 0; ni < 4; ni++) {
                int nf = wn * 4 + ni;
                b[ni] = *(const uint2*)&Bs[((nf * 16 + k8) * 32 + lane) * 2];
            }
#pragma unroll
            for (int mi = 0; mi < 4; mi++)
#pragma unroll
                for (int ni = 0; ni < 4; ni++)
                    mma_tf32(acc[mi][ni], a[mi], b[ni]);
        }
        __syncthreads();                       // Bs fully consumed
        if (t + 1 < t_hi) cp_B(Bs, t + 1, tid);

        // spill acc -> sb (pitch 136 to dodge STS.64 conflicts)
        {
            int g  = lane >> 2;
            int c2 = (lane & 3) * 2;
#pragma unroll
            for (int mi = 0; mi < 4; mi++) {
                int ra = wm * 64 + mi * 16 + g;
#pragma unroll
                for (int ni = 0; ni < 4; ni++) {
                    int c = wn * 32 + ni * 8 + c2;
                    *(float2*)&sb[ra * 136 + c]       = make_float2(acc[mi][ni][0], acc[mi][ni][1]);
                    *(float2*)&sb[(ra + 8) * 136 + c] = make_float2(acc[mi][ni][2], acc[mi][ni][3]);
                }
            }
        }
        __syncthreads();

        // streaming candidate scan: 2 threads/row, skewed conflict-free
        int n0 = t * 128;
#pragma unroll 4
        for (int s = 0; s < 64; s++) {
            int col = (half << 6) + ((s + row) & 63);
            float v = sb[row * 136 + col];
            if (v > tv[11]) {
                int j = n0 + col;
                if (j < NYC) insert12(tv, ti, v, j);
            }
        }
        // next-iter top-of-loop wait+sync orders scan before next spill
    }

    int m = mtile * 128 + row;
#pragma unroll
    for (int q = 0; q < 12; q++)
        g_candI[m * NCAND + (split * 2 + half) * DEPTH + q] = ti[q];
}

// ---------------- exact fp32 rescore (bitwise-identical chain) + softmax + COO ----------------
__global__ __launch_bounds__(128) void rescore_kernel(float* __restrict__ out) {
    extern __shared__ float rs[];
    float* xrow  = rs;                        // 128
    float* yrows = rs + 128;                  // 96 * 129 (pitch 129 -> conflict-free)
    float* vals  = yrows + 96 * 129;          // 96
    int*   cols  = (int*)(vals + 96);         // 96

    const int m = blockIdx.x;
    const int tid = threadIdx.x;

    if (tid < 128) xrow[tid] = g_x32[m * CDIM + tid];
    if (tid < 96)  cols[tid] = g_candI[m * NCAND + tid];
    __syncthreads();

    for (int i = tid; i < 96 * 32; i += 128) {
        int c = i >> 5, p = i & 31;
        float4 v = *(const float4*)&g_y32[(size_t)cols[c] * CDIM + p * 4];
        float* dst = &yrows[c * 129 + p * 4];
        dst[0] = v.x; dst[1] = v.y; dst[2] = v.z; dst[3] = v.w;
    }
    __syncthreads();

    if (tid < 96) {
        // EXACT sequential fp32 fma chain, k ascending, acc=0 — matches R2 values bitwise
        float s = 0.0f;
        const float* yr = &yrows[tid * 129];
#pragma unroll 16
        for (int k = 0; k < 128; k++) s = fmaf(xrow[k], yr[k], s);
        vals[tid] = s;
    }
    __syncthreads();

    if (tid == 0) {
        float tv[10]; int tix[10];
#pragma unroll
        for (int q = 0; q < 10; q++) { tv[q] = -__int_as_float(0x7f800000); tix[q] = 0x7fffffff; }
        for (int c = 0; c < 96; c++) {
            float v = vals[c]; int j = cols[c];
            if (v > tv[9] || (v == tv[9] && j < tix[9])) insert10(tv, tix, v, j);
        }
        float mx = tv[0];
        float e[10], sum = 0.0f;
#pragma unroll
        for (int q = 0; q < 10; q++) { e[q] = expf((tv[q] - mx) * INV_TAU); sum += e[q]; }
        float inv = 1.0f / sum;
#pragma unroll
        for (int q = 0; q < 10; q++) {
            out[m * 10 + q]           = e[q] * inv;
            out[NXK + m * 10 + q]     = (float)m;
            out[2 * NXK + m * 10 + q] = (float)tix[q];
        }
    }
}

// ---------------- launch ----------------
extern "C" void kernel_launch(void* const* d_in, const int* in_sizes, int n_in,
                              void* d_out, int out_size) {
    const float* fx = (const float*)d_in[0];
    const float* fy = (const float*)d_in[1];
    if (n_in >= 2 && in_sizes[0] == NYC * CDIM && in_sizes[1] == NXC * CDIM) {
        const float* t = fx; fx = fy; fy = t;
    }
    float* outF = (float*)d_out;

    cudaFuncSetAttribute(gemm_topk_kernel,
                         cudaFuncAttributeMaxDynamicSharedMemorySize, 200704);
    cudaFuncSetAttribute(rescore_kernel,
                         cudaFuncAttributeMaxDynamicSharedMemorySize, 50816);

    norm_x_kernel<<<NXC / 8, 256>>>(fx);
    norm_y_kernel<<<NY_PAD / 8, 256>>>(fy);
    pack_x_kernel<<<(NXC * 32) / 256, 256>>>();
    pack_y_kernel<<<(NY_PAD * 64) / 256, 256>>>();
    gemm_topk_kernel<<<dim3(NXC / 128, NSPLIT), 256, 200704>>>();
    rescore_kernel<<<NXC, 128, 50816>>>(outF);
}